// round 1
// baseline (speedup 1.0000x reference)
#include <cuda_runtime.h>
#include <math.h>

// Problem shapes (fixed by dataset)
#define BQ   2
#define NQ   512
#define NABC 128
#define NFC  128
#define NGC  32
#define ROWS (BQ * NQ)   // 1024

typedef unsigned long long u64;

// Scratch: rf = r @ W_af, [B, N, F]
__device__ float g_rf[ROWS * NFC];

// ---------------- packed f32x2 helpers (sm_103a FFMA2) ----------------
__device__ __forceinline__ u64 pk2(float a, float b) {
    u64 r;
    asm("mov.b64 %0, {%1, %2};" : "=l"(r)
        : "r"(__float_as_uint(a)), "r"(__float_as_uint(b)));
    return r;
}
__device__ __forceinline__ u64 dup2(float a) { return pk2(a, a); }
__device__ __forceinline__ u64 f2fma(u64 a, u64 b, u64 c) {
    u64 d;
    asm("fma.rn.f32x2 %0, %1, %2, %3;" : "=l"(d) : "l"(a), "l"(b), "l"(c));
    return d;
}
__device__ __forceinline__ u64 f2mul(u64 a, u64 b) {
    u64 d;
    asm("mul.rn.f32x2 %0, %1, %2;" : "=l"(d) : "l"(a), "l"(b));
    return d;
}
__device__ __forceinline__ u64 f2add(u64 a, u64 b) {
    u64 d;
    asm("add.rn.f32x2 %0, %1, %2;" : "=l"(d) : "l"(a), "l"(b));
    return d;
}
__device__ __forceinline__ float hsum2(u64 v) {
    unsigned int x, y;
    asm("mov.b64 {%0, %1}, %2;" : "=r"(x), "=r"(y) : "l"(v));
    return __uint_as_float(x) + __uint_as_float(y);
}

// shifted softplus: ln(1+e^x) - ln 2
__device__ __forceinline__ float ssp(float x) {
    float sp = fmaxf(x, 0.0f) + log1pf(__expf(-fabsf(x)));
    return sp - 0.6931471805599453f;
}

// ---------------- kernel A: rf[row, f] = sum_k r[row, k] * W_af[k, f] ----------------
__global__ void __launch_bounds__(128) rf_kernel(const float* __restrict__ r,
                                                 const float* __restrict__ W_af) {
    int row = blockIdx.x;
    int t = threadIdx.x;
    __shared__ float rS[NABC];
    rS[t] = r[(size_t)row * NABC + t];
    __syncthreads();
    float acc = 0.0f;
#pragma unroll 8
    for (int k = 0; k < NABC; k++) acc = fmaf(rS[k], W_af[k * NFC + t], acc);
    g_rf[(size_t)row * NFC + t] = acc;
}

// ---------------- kernel B: fused smearing + filter GEMM + cfconv + dense/dense ----------------
// Dynamic shared layout (floats):
//   esS   [NG][NQ]   transposed smearing values   16384
//   W2S   [NG][NF]                                 4096
//   eS    [NQ]                                      512
//   aS    [NQ]                                      512
//   ySh   [8][NF]    per-warp partials             1024
//   offS  [NG], coefS[NG]                             64
#define SMEM_FLOATS (NGC * NQ + NGC * NFC + NQ + NQ + 8 * NFC + 2 * NGC)
#define SMEM_BYTES  (SMEM_FLOATS * 4)

__global__ void __launch_bounds__(256, 2)
main_kernel(const float* __restrict__ e, const float* __restrict__ A,
            const float* __restrict__ offsets, const float* __restrict__ widths,
            const float* __restrict__ W_df2, const float* __restrict__ b_df2,
            const float* __restrict__ W_d1, const float* __restrict__ b_d1,
            const float* __restrict__ W_d2, const float* __restrict__ b_d2,
            float* __restrict__ out) {
    extern __shared__ float smem[];
    float* esS   = smem;                    // [NG][NQ]
    float* W2S   = esS + NGC * NQ;          // [NG][NF]
    float* eS    = W2S + NGC * NFC;         // [NQ]
    float* aS    = eS + NQ;                 // [NQ]
    float* ySh   = aS + NQ;                 // [8][NF]
    float* offS  = ySh + 8 * NFC;           // [NG]
    float* coefS = offS + NGC;              // [NG]

    const int row = blockIdx.x;             // b*N + i
    const int b   = row >> 9;
    const int tid = threadIdx.x;

    // Phase 0: stage rows + weights
    const float* erow = e + (size_t)row * NQ;
    const float* arow = A + (size_t)row * NQ;
    for (int idx = tid; idx < NQ; idx += 256) {
        eS[idx] = erow[idx];
        aS[idx] = arow[idx];
    }
    for (int idx = tid; idx < NGC * NFC; idx += 256) W2S[idx] = W_df2[idx];
    if (tid < NGC) {
        float w0 = widths[tid];
        coefS[tid] = -0.5f / (w0 * w0);
        offS[tid]  = offsets[tid];
    }
    __syncthreads();

    // Phase 1: Gaussian smearing, transposed [g][j]
    for (int idx = tid; idx < NGC * NQ; idx += 256) {
        int g = idx >> 9;
        int j = idx & (NQ - 1);
        float d = eS[j] - offS[g];
        esS[idx] = __expf(coefS[g] * d * d);
    }
    __syncthreads();

    // Phase 2: per-warp j-range, packed f32x2 contraction
    const int warp = tid >> 5;
    const int lane = tid & 31;
    const int f0   = lane << 2;                 // 4 f-values per lane
    const float* rfb = g_rf + (size_t)b * NQ * NFC;

    const float4 b2v = *(const float4*)(b_df2 + f0);
    u64 b2d[4] = {dup2(b2v.x), dup2(b2v.y), dup2(b2v.z), dup2(b2v.w)};
    u64 acc[4] = {0ull, 0ull, 0ull, 0ull};      // pairs over (even j, odd j)

    const int j_beg = warp * 64;
    for (int jt = j_beg; jt < j_beg + 64; jt += 8) {
        // Prefetch rf (packed across jj pairs) and A row values
        u64 rfP[4][4];
        u64 aP[4];
#pragma unroll
        for (int p = 0; p < 4; p++) {
            const float4 v0 = *(const float4*)(rfb + (size_t)(jt + 2 * p) * NFC + f0);
            const float4 v1 = *(const float4*)(rfb + (size_t)(jt + 2 * p + 1) * NFC + f0);
            rfP[p][0] = pk2(v0.x, v1.x);
            rfP[p][1] = pk2(v0.y, v1.y);
            rfP[p][2] = pk2(v0.z, v1.z);
            rfP[p][3] = pk2(v0.w, v1.w);
            const float2 a2 = *(const float2*)(aS + jt + 2 * p);
            aP[p] = pk2(a2.x, a2.y);
        }

        u64 wp[4][4];
#pragma unroll
        for (int p = 0; p < 4; p++)
#pragma unroll
            for (int k = 0; k < 4; k++) wp[p][k] = 0ull;

#pragma unroll 8
        for (int g = 0; g < NGC; g++) {
            const float4 Wv = *(const float4*)(W2S + g * NFC + f0);
            u64 Wd0 = dup2(Wv.x), Wd1 = dup2(Wv.y), Wd2 = dup2(Wv.z), Wd3 = dup2(Wv.w);
            const u64* esrow = (const u64*)(esS + g * NQ + jt);
#pragma unroll
            for (int p = 0; p < 4; p++) {
                u64 esp = esrow[p];
                wp[p][0] = f2fma(esp, Wd0, wp[p][0]);
                wp[p][1] = f2fma(esp, Wd1, wp[p][1]);
                wp[p][2] = f2fma(esp, Wd2, wp[p][2]);
                wp[p][3] = f2fma(esp, Wd3, wp[p][3]);
            }
        }

        // acc += (w + b_df2) * (A * rf)
#pragma unroll
        for (int p = 0; p < 4; p++) {
#pragma unroll
            for (int k = 0; k < 4; k++) {
                u64 arf = f2mul(aP[p], rfP[p][k]);
                acc[k] = f2fma(f2add(wp[p][k], b2d[k]), arf, acc[k]);
            }
        }
    }

    // Per-warp partials -> shared
#pragma unroll
    for (int k = 0; k < 4; k++) ySh[warp * NFC + f0 + k] = hsum2(acc[k]);
    __syncthreads();

    // Reduce over 8 warps into eS (reused as y row)
    if (tid < NFC) {
        float yv = 0.0f;
#pragma unroll
        for (int w = 0; w < 8; w++) yv += ySh[w * NFC + tid];
        eS[tid] = yv;
    }
    __syncthreads();

    // Epilogue stage 1: h = ssp(y @ W_d1 + b_d1)
    if (tid < NFC) {
        float h = b_d1[tid];
#pragma unroll 8
        for (int k = 0; k < NFC; k++) h = fmaf(eS[k], W_d1[k * NABC + tid], h);
        aS[tid] = ssp(h);
    }
    __syncthreads();

    // Epilogue stage 2: out = h @ W_d2 + b_d2
    if (tid < NFC) {
        float o = b_d2[tid];
#pragma unroll 8
        for (int k = 0; k < NABC; k++) o = fmaf(aS[k], W_d2[k * NABC + tid], o);
        out[(size_t)row * NABC + tid] = o;
    }
}

// ---------------- launch ----------------
extern "C" void kernel_launch(void* const* d_in, const int* in_sizes, int n_in,
                              void* d_out, int out_size) {
    const float* r      = (const float*)d_in[0];
    const float* e      = (const float*)d_in[1];
    const float* A      = (const float*)d_in[2];
    const float* offs   = (const float*)d_in[3];
    const float* wid    = (const float*)d_in[4];
    // d_in[5] = W_df1, d_in[6] = b_df1: outputs discarded by reference -> skipped
    const float* W_df2  = (const float*)d_in[7];
    const float* b_df2  = (const float*)d_in[8];
    const float* W_af   = (const float*)d_in[9];
    const float* W_d1   = (const float*)d_in[10];
    const float* b_d1   = (const float*)d_in[11];
    const float* W_d2   = (const float*)d_in[12];
    const float* b_d2   = (const float*)d_in[13];
    float* out = (float*)d_out;

    rf_kernel<<<ROWS, 128>>>(r, W_af);

    cudaFuncSetAttribute(main_kernel, cudaFuncAttributeMaxDynamicSharedMemorySize,
                         SMEM_BYTES);
    main_kernel<<<ROWS, 256, SMEM_BYTES>>>(e, A, offs, wid, W_df2, b_df2,
                                           W_d1, b_d1, W_d2, b_d2, out);
}

// round 3
// speedup vs baseline: 1.3540x; 1.3540x over previous
#include <cuda_runtime.h>
#include <cuda_bf16.h>
#include <math.h>
#include <stdint.h>

#define NQ  512
#define NF  128
#define NG  32
#define RPC 4
#define KC  64
#define NKC (NQ / KC)      // 8
#define GRID (1024 / RPC)  // 256

// rf transposed, bf16 hi/lo split: [2 b][128 f][512 j]
__device__ __nv_bfloat16 g_rfT_hi[2 * NF * NQ];
__device__ __nv_bfloat16 g_rfT_lo[2 * NF * NQ];

// ---------------- helpers ----------------
__device__ __forceinline__ uint32_t smem_u32(const void* p) {
    uint32_t a;
    asm("{ .reg .u64 t; cvta.to.shared.u64 t, %1; cvt.u32.u64 %0, t; }" : "=r"(a) : "l"(p));
    return a;
}
__device__ __forceinline__ float ssp(float x) {
    float sp = fmaxf(x, 0.0f) + log1pf(__expf(-fabsf(x)));
    return sp - 0.6931471805599453f;
}

#define LDSM4(R, addr) \
    asm volatile("ldmatrix.sync.aligned.m8n8.x4.shared.b16 {%0,%1,%2,%3}, [%4];" \
        : "=r"((R)[0]), "=r"((R)[1]), "=r"((R)[2]), "=r"((R)[3]) : "r"(addr))

#define MMA(D, Aa, B0, B1) \
    asm volatile("mma.sync.aligned.m16n8k16.row.col.f32.bf16.bf16.f32 " \
        "{%0,%1,%2,%3}, {%4,%5,%6,%7}, {%8,%9}, {%0,%1,%2,%3};" \
        : "+f"((D)[0]), "+f"((D)[1]), "+f"((D)[2]), "+f"((D)[3]) \
        : "r"((Aa)[0]), "r"((Aa)[1]), "r"((Aa)[2]), "r"((Aa)[3]), "r"(B0), "r"(B1))

#define CP_ASYNC16(dst, src) \
    asm volatile("cp.async.cg.shared.global [%0], [%1], 16;" :: "r"(dst), "l"(src))

// ---------------- smem layout (bytes) ----------------
// A tiles: [2 split][128 f][64 j] bf16, row stride 144B (128 data + 16 pad)
#define A_SPLIT_SZ (NF * 144)          // 18432
#define A_SZ       (2 * A_SPLIT_SZ)    // 36864
// B tiles: [4 rr][2 split][48 g][64 j] bf16, row stride 144B
#define B_SPLIT_SZ (48 * 144)          // 6912
#define B_ROW_SZ   (2 * B_SPLIT_SZ)    // 13824
#define B_SZ       (RPC * B_ROW_SZ)    // 55296
#define AOFF  0
#define BOFF  A_SZ
#define YOFF  (BOFF + B_SZ)            // 92160
#define OFFS_OFF (YOFF + RPC * NF * 4) // 94208
#define COEF_OFF (OFFS_OFF + 160)
#define SMEM_TOTAL (COEF_OFF + 160)    // 94528
#define HOFF  AOFF                     // hS aliases A region (dead by then)

// ---------------- kernel A: rf = r @ W_af -> transposed bf16 hi/lo ----------------
__global__ void __launch_bounds__(256) rf_kernel(const float* __restrict__ r,
                                                 const float* __restrict__ W_af) {
    __shared__ float Ws[NF * NF];   // 64KB
    __shared__ float rsT[NF * 32];  // [k][jj] 16KB
    const int b = blockIdx.x >> 4, jt = blockIdx.x & 15, j0 = jt * 32;
    const int t = threadIdx.x;

    for (int i = t; i < NF * NF / 4; i += 256)
        ((float4*)Ws)[i] = ((const float4*)W_af)[i];
    for (int i = t; i < 32 * NF / 4; i += 256) {
        int jj = i >> 5, k4 = i & 31;
        float4 v = ((const float4*)(r + (size_t)(b * NQ + j0 + jj) * NF))[k4];
        rsT[(k4 * 4 + 0) * 32 + jj] = v.x;
        rsT[(k4 * 4 + 1) * 32 + jj] = v.y;
        rsT[(k4 * 4 + 2) * 32 + jj] = v.z;
        rsT[(k4 * 4 + 3) * 32 + jj] = v.w;
    }
    __syncthreads();

    const int f = t & 127, jh = t >> 7;
    __nv_bfloat16* dh = g_rfT_hi + (size_t)(b * NF + f) * NQ + j0;
    __nv_bfloat16* dl = g_rfT_lo + (size_t)(b * NF + f) * NQ + j0;
#pragma unroll
    for (int jg = 0; jg < 4; jg++) {
        const int jjb = jh * 16 + jg * 4;
        float a0 = 0, a1 = 0, a2 = 0, a3 = 0;
#pragma unroll 8
        for (int k = 0; k < NF; k++) {
            float w = Ws[k * NF + f];
            float4 rv = *(const float4*)&rsT[k * 32 + jjb];
            a0 = fmaf(rv.x, w, a0);
            a1 = fmaf(rv.y, w, a1);
            a2 = fmaf(rv.z, w, a2);
            a3 = fmaf(rv.w, w, a3);
        }
        __nv_bfloat162 h01 = __floats2bfloat162_rn(a0, a1);
        __nv_bfloat162 h23 = __floats2bfloat162_rn(a2, a3);
        __nv_bfloat162 l01 = __floats2bfloat162_rn(a0 - __low2float(h01), a1 - __high2float(h01));
        __nv_bfloat162 l23 = __floats2bfloat162_rn(a2 - __low2float(h23), a3 - __high2float(h23));
        *(__nv_bfloat162*)(dh + jjb)     = h01;
        *(__nv_bfloat162*)(dh + jjb + 2) = h23;
        *(__nv_bfloat162*)(dl + jjb)     = l01;
        *(__nv_bfloat162*)(dl + jjb + 2) = l23;
    }
}

// ---------------- main kernel ----------------
__global__ void __launch_bounds__(256, 2)
main_kernel(const float* __restrict__ e, const float* __restrict__ A,
            const float* __restrict__ offsets, const float* __restrict__ widths,
            const float* __restrict__ W_df2, const float* __restrict__ b_df2,
            const float* __restrict__ W_d1, const float* __restrict__ b_d1,
            const float* __restrict__ W_d2, const float* __restrict__ b_d2,
            float* __restrict__ out) {
    extern __shared__ char sm[];
    const uint32_t sb = smem_u32(sm);
    const int tid = threadIdx.x, w = tid >> 5, l = tid & 31;
    const int g0 = blockIdx.x * RPC, b = g0 >> 9;

    float* yS   = (float*)(sm + YOFF);
    float* offS = (float*)(sm + OFFS_OFF);
    float* coefS = (float*)(sm + COEF_OFF);

    // zero entire B buffer (pad rows 33..47 stay zero forever)
    for (int i = tid; i < B_SZ / 4; i += 256) ((float*)(sm + BOFF))[i] = 0.0f;
    if (tid < 32) {
        float w0 = widths[tid];
        coefS[tid] = -0.5f / (w0 * w0);
        offS[tid] = offsets[tid];
    }
    __syncthreads();

    // producer role: warp -> (row prr, g-half pgh); lane -> j pair 2*l
    const int prr = w >> 1, pgh = w & 1;
    const int pg_lo = pgh ? 17 : 0, pg_hi = pgh ? 33 : 17;
    const float* erow = e + (size_t)(g0 + prr) * NQ;
    const float* arow = A + (size_t)(g0 + prr) * NQ;
    char* bB = sm + BOFF + prr * B_ROW_SZ;

    // mma role: warp -> (row rr, m-half mh)
    const int rr = w >> 1, mh = w & 1, m0 = mh * 64;

    float acc[4][5][4];
#pragma unroll
    for (int mt = 0; mt < 4; mt++)
#pragma unroll
        for (int nt = 0; nt < 5; nt++)
#pragma unroll
            for (int d = 0; d < 4; d++) acc[mt][nt][d] = 0.0f;

    const __nv_bfloat16* rfh = g_rfT_hi + (size_t)b * NF * NQ;
    const __nv_bfloat16* rfl = g_rfT_lo + (size_t)b * NF * NQ;

    for (int kc = 0; kc < NKC; kc++) {
        const int j0 = kc * KC;

        // A tiles via cp.async: 2048 x 16B, 8 per thread
#pragma unroll
        for (int i = 0; i < 8; i++) {
            int id = tid * 8 + i;
            int s = id >> 10, f = (id >> 3) & 127, q = id & 7;
            const __nv_bfloat16* src = (s ? rfl : rfh) + (size_t)f * NQ + j0 + q * 8;
            uint32_t dst = sb + AOFF + s * A_SPLIT_SZ + f * 144 + q * 16;
            CP_ASYNC16(dst, src);
        }
        asm volatile("cp.async.commit_group;");

        // B produce: es' = A[j]*exp(coef*(e[j]-off)^2), row 32 = A[j]; bf16 hi/lo
        {
            float2 ev = *(const float2*)(erow + j0 + 2 * l);
            float2 av = *(const float2*)(arow + j0 + 2 * l);
            for (int g = pg_lo; g < pg_hi; g++) {
                float v0, v1;
                if (g < 32) {
                    float off = offS[g], c = coefS[g];
                    float d0 = ev.x - off, d1 = ev.y - off;
                    v0 = av.x * __expf(c * d0 * d0);
                    v1 = av.y * __expf(c * d1 * d1);
                } else { v0 = av.x; v1 = av.y; }
                __nv_bfloat162 h2 = __floats2bfloat162_rn(v0, v1);
                __nv_bfloat162 l2 = __floats2bfloat162_rn(v0 - __low2float(h2),
                                                          v1 - __high2float(h2));
                *(__nv_bfloat162*)(bB + g * 144 + 4 * l) = h2;
                *(__nv_bfloat162*)(bB + B_SPLIT_SZ + g * 144 + 4 * l) = l2;
            }
        }
        asm volatile("cp.async.wait_group 0;" ::: "memory");
        __syncthreads();

        // mma: 4 k16-steps
        const uint32_t aBase = sb + AOFF;
        const uint32_t bBase = sb + BOFF + rr * B_ROW_SZ;
        const int grow = (l & 7) + ((l >> 4) << 3);
        const int bkh = (l >> 3) & 1;
        const int arw = (l & 15), akh = l >> 4;
#pragma unroll
        for (int k16 = 0; k16 < 4; k16++) {
            uint32_t bh[3][4], bl[3][4];
#pragma unroll
            for (int p = 0; p < 3; p++) {
                uint32_t addr = bBase + (uint32_t)(p * 16 + grow) * 144 + k16 * 32 + bkh * 16;
                LDSM4(bh[p], addr);
                LDSM4(bl[p], addr + B_SPLIT_SZ);
            }
#pragma unroll
            for (int mt = 0; mt < 4; mt++) {
                uint32_t aaddr = aBase + (uint32_t)(m0 + mt * 16 + arw) * 144 + k16 * 32 + akh * 16;
                uint32_t ah[4], al[4];
                LDSM4(ah, aaddr);
                LDSM4(al, aaddr + A_SPLIT_SZ);
#pragma unroll
                for (int nt = 0; nt < 5; nt++) {
                    const uint32_t b0h = bh[nt >> 1][(nt & 1) * 2];
                    const uint32_t b1h = bh[nt >> 1][(nt & 1) * 2 + 1];
                    const uint32_t b0l = bl[nt >> 1][(nt & 1) * 2];
                    const uint32_t b1l = bl[nt >> 1][(nt & 1) * 2 + 1];
                    MMA(acc[mt][nt], ah, b0h, b1h);
                    MMA(acc[mt][nt], ah, b0l, b1l);
                    MMA(acc[mt][nt], al, b0h, b1h);
                }
            }
        }
        __syncthreads();   // mma reads done before next produce overwrites A/B
    }

    // Epilogue 1: y[f] = sum_g C[f,g]*W2[g,f] + C[f,32]*b2[f]
    {
        const int r_lo = l >> 2, cb = 2 * (l & 3);
#pragma unroll
        for (int mt = 0; mt < 4; mt++) {
            const int f0v = m0 + mt * 16 + r_lo;
            const int f1v = f0v + 8;
            float y0 = 0.0f, y1 = 0.0f;
#pragma unroll
            for (int nt = 0; nt < 5; nt++) {
#pragma unroll
                for (int s = 0; s < 2; s++) {
                    const int g = nt * 8 + cb + s;
                    if (g < 32) {
                        y0 = fmaf(acc[mt][nt][s],     W_df2[g * NF + f0v], y0);
                        y1 = fmaf(acc[mt][nt][2 + s], W_df2[g * NF + f1v], y1);
                    } else if (g == 32) {
                        y0 = fmaf(acc[mt][nt][s],     b_df2[f0v], y0);
                        y1 = fmaf(acc[mt][nt][2 + s], b_df2[f1v], y1);
                    }
                }
            }
            y0 += __shfl_xor_sync(0xFFFFFFFFu, y0, 1);
            y0 += __shfl_xor_sync(0xFFFFFFFFu, y0, 2);
            y1 += __shfl_xor_sync(0xFFFFFFFFu, y1, 1);
            y1 += __shfl_xor_sync(0xFFFFFFFFu, y1, 2);
            if ((l & 3) == 0) {
                yS[rr * NF + f0v] = y0;
                yS[rr * NF + f1v] = y1;
            }
        }
    }
    __syncthreads();

    // Epilogue 2: two dense layers (hS aliases dead A region)
    {
        float* hS = (float*)(sm + HOFF);
        const int f = tid & 127, r0i = tid >> 7;
        float h0 = b_d1[f], h1 = h0;
#pragma unroll 8
        for (int k = 0; k < NF; k++) {
            float wv = W_d1[k * NF + f];
            h0 = fmaf(yS[r0i * NF + k], wv, h0);
            h1 = fmaf(yS[(r0i + 2) * NF + k], wv, h1);
        }
        hS[r0i * NF + f] = ssp(h0);
        hS[(r0i + 2) * NF + f] = ssp(h1);
        __syncthreads();
        float o0 = b_d2[f], o1 = o0;
#pragma unroll 8
        for (int k = 0; k < NF; k++) {
            float wv = W_d2[k * NF + f];
            o0 = fmaf(hS[r0i * NF + k], wv, o0);
            o1 = fmaf(hS[(r0i + 2) * NF + k], wv, o1);
        }
        out[(size_t)(g0 + r0i) * NF + f] = o0;
        out[(size_t)(g0 + r0i + 2) * NF + f] = o1;
    }
}

// ---------------- launch ----------------
extern "C" void kernel_launch(void* const* d_in, const int* in_sizes, int n_in,
                              void* d_out, int out_size) {
    const float* r     = (const float*)d_in[0];
    const float* e     = (const float*)d_in[1];
    const float* A     = (const float*)d_in[2];
    const float* offs  = (const float*)d_in[3];
    const float* wid   = (const float*)d_in[4];
    // d_in[5]=W_df1, d_in[6]=b_df1: outputs discarded by reference
    const float* W_df2 = (const float*)d_in[7];
    const float* b_df2 = (const float*)d_in[8];
    const float* W_af  = (const float*)d_in[9];
    const float* W_d1  = (const float*)d_in[10];
    const float* b_d1  = (const float*)d_in[11];
    const float* W_d2  = (const float*)d_in[12];
    const float* b_d2  = (const float*)d_in[13];
    float* out = (float*)d_out;

    rf_kernel<<<32, 256>>>(r, W_af);

    cudaFuncSetAttribute(main_kernel, cudaFuncAttributeMaxDynamicSharedMemorySize,
                         SMEM_TOTAL);
    main_kernel<<<GRID, 256, SMEM_TOTAL>>>(e, A, offs, wid, W_df2, b_df2,
                                           W_d1, b_d1, W_d2, b_d2, out);
}